// round 3
// baseline (speedup 1.0000x reference)
#include <cuda_runtime.h>
#include <math.h>

#define BB 4096
#define TT 750
#define WIN 11
#define NSN (TT * WIN)         // 8250
#define NBZ 128                // blocks for ns partial pass
#define ROWS_PER_BLK (BB / NBZ) // 32
#define NS_SKIP_THRESH 176.0f  // exp(-88) ~ 6e-39: contribution negligible vs loss ~12.5

// Scratch (static device globals; no allocation allowed)
__device__ float g_ns_part[NBZ * NSN];   // 4.2 MB
__device__ float g_ns[NSN];
__device__ unsigned int g_mask[TT];
__device__ float g_partial[BB];

// ---------------------------------------------------------------------------
// Kernel A1: interior ns partials. Block z handles 32 rows of `a`.
// ns[t][w] interior terms: (a[b,t] - a[b, t+w-6])^2 for 6 <= t+w < 756.
// Edge terms (t+w<6 or t+w>=756) use the reference's SCRAMBLED tile-padding
// (other rows' first/last elements) and are handled in k_ns_edge.
// ---------------------------------------------------------------------------
__global__ __launch_bounds__(256) void k_ns_part(const float* __restrict__ a) {
    __shared__ float srow[TT];
    const int z = blockIdx.x;
    const int tid = threadIdx.x;

    float acc[3][WIN];
#pragma unroll
    for (int k = 0; k < 3; k++)
#pragma unroll
        for (int w = 0; w < WIN; w++) acc[k][w] = 0.0f;

    for (int r = 0; r < ROWS_PER_BLK; r++) {
        const int b = z * ROWS_PER_BLK + r;
        const float* __restrict__ row = a + (size_t)b * TT;
        for (int j = tid; j < TT; j += 256) srow[j] = row[j];
        __syncthreads();
#pragma unroll
        for (int k = 0; k < 3; k++) {
            const int t = tid + k * 256;
            if (t < TT) {
                const float at = srow[t];
#pragma unroll
                for (int w = 0; w < WIN; w++) {
                    const int j = t + w;           // padded index
                    if (j >= 6 && j < TT + 6) {    // interior
                        const float d = at - srow[j - 6];
                        acc[k][w] += d * d;
                    }
                }
            }
        }
        __syncthreads();
    }
#pragma unroll
    for (int k = 0; k < 3; k++) {
        const int t = tid + k * 256;
        if (t < TT) {
#pragma unroll
            for (int w = 0; w < WIN; w++)
                g_ns_part[(size_t)z * NSN + t * WIN + w] = acc[k][w];
        }
    }
}

// ---------------------------------------------------------------------------
// Kernel A2: reduce partials -> g_ns (fixed order, deterministic)
// ---------------------------------------------------------------------------
__global__ __launch_bounds__(256) void k_ns_reduce() {
    const int idx = blockIdx.x * 256 + threadIdx.x;
    if (idx < NSN) {
        float s = 0.0f;
        for (int z = 0; z < NBZ; z++) s += g_ns_part[(size_t)z * NSN + idx];
        g_ns[idx] = s;
    }
}

// ---------------------------------------------------------------------------
// Kernel A3: 31 edge (t,w) pairs with the reference's scrambled pad:
//   front (j=t+w<6):  pad value = a[(6*b+j)%B, 0]
//   back  (j>=756):   pad value = a[(6*b+(j-755))%B, T-1]
// One block per pair; block-reduce over b. Overwrites g_ns edge slots.
// ---------------------------------------------------------------------------
__global__ __launch_bounds__(256) void k_ns_edge(const float* __restrict__ a) {
    const int p = blockIdx.x;
    int t = 0, w = 0;
    if (p < 21) {
        // front pairs: t=0..5, w in [0, 5-t], counts 6,5,4,3,2,1
        int acc = 0;
        for (int tt = 0; tt < 6; tt++) {
            const int c = 6 - tt;
            if (p < acc + c) { t = tt; w = p - acc; break; }
            acc += c;
        }
    } else {
        // back pairs: t=746..749, w >= 756-t, counts 1,2,3,4
        const int q = p - 21;
        int acc = 0;
        for (int tt = 746; tt < 750; tt++) {
            const int c = tt - 745;
            if (q < acc + c) { t = tt; w = (756 - tt) + (q - acc); break; }
            acc += c;
        }
    }
    const int j = t + w;

    __shared__ float red[256];
    const int tid = threadIdx.x;
    float s = 0.0f;
    for (int b = tid; b < BB; b += 256) {
        float pv;
        if (j < 6) pv = a[(size_t)((6 * b + j) & (BB - 1)) * TT];
        else       pv = a[(size_t)((6 * b + (j - 755)) & (BB - 1)) * TT + (TT - 1)];
        const float d = a[(size_t)b * TT + t] - pv;
        s += d * d;
    }
    red[tid] = s;
    __syncthreads();
    for (int st = 128; st > 0; st >>= 1) {
        if (tid < st) red[tid] += red[tid + st];
        __syncthreads();
    }
    if (tid == 0) g_ns[t * WIN + w] = red[0];
}

// ---------------------------------------------------------------------------
// Kernel A4: per-t survivor mask (ns <= thresh -> exp not flushed to ~0)
// ---------------------------------------------------------------------------
__global__ __launch_bounds__(256) void k_mask() {
    const int t = blockIdx.x * 256 + threadIdx.x;
    if (t < TT) {
        unsigned m = 0;
#pragma unroll
        for (int w = 0; w < WIN; w++)
            if (g_ns[t * WIN + w] <= NS_SKIP_THRESH) m |= (1u << w);
        g_mask[t] = m;
    }
}

// ---------------------------------------------------------------------------
// Kernel B: main pass. Block i handles row i.
//   term1_i = sum_{t,w} exp(-max(ns,g)/2) * |a2[i,t] - a3_win|  (filtered)
//   term2_i = sum_t (a[i,t]-a2[i,t])^2
// Filter: ns > thresh  -> weight == 0 in f32 (skip);
//         d2 == 0      -> product exactly 0 (skip).
// Rare surviving terms take the full faithful path (max_w over tiled rows).
// ---------------------------------------------------------------------------
__global__ __launch_bounds__(256) void k_main(const float* __restrict__ a,
                                              const float* __restrict__ a2) {
    const int i = blockIdx.x;
    const int tid = threadIdx.x;
    const float* __restrict__ ra  = a  + (size_t)i * TT;
    const float* __restrict__ ra2 = a2 + (size_t)i * TT;

    float acc1 = 0.0f;  // sum w*d2
    float acc2 = 0.0f;  // sum diff^2

    for (int t = tid; t < TT; t += 256) {
        const float av  = ra[t];
        const float a2v = ra2[t];
        const float dd = av - a2v;
        acc2 += dd * dd;

        unsigned m = g_mask[t];
        while (m) {
            const int w = __ffs(m) - 1;
            m &= m - 1;
            const int j = t + w;
            // a3_win (a2 with scrambled pad)
            float a3w;
            if (j < 6)            a3w = a2[(size_t)((6 * i + j) & (BB - 1)) * TT];
            else if (j < TT + 6)  a3w = ra2[j - 6];
            else                  a3w = a2[(size_t)((6 * i + (j - 755)) & (BB - 1)) * TT + (TT - 1)];
            const float d2 = fabsf(a2v - a3w);
            if (d2 != 0.0f) {
                // Rare path: compute g[i,t] = (max_w2 (tiled - a4_win))^2
                float mx = -3.0e38f;
#pragma unroll
                for (int w2 = 0; w2 < WIN; w2++) {
                    const int j2 = t + w2;
                    float a4w;
                    if (j2 < 6)           a4w = a[(size_t)((6 * i + j2) & (BB - 1)) * TT];
                    else if (j2 < TT + 6) a4w = ra[j2 - 6];
                    else                  a4w = a[(size_t)((6 * i + (j2 - 755)) & (BB - 1)) * TT + (TT - 1)];
                    const float tv = a[(size_t)((11 * i + w2) & (BB - 1)) * TT + t];
                    mx = fmaxf(mx, tv - a4w);
                }
                const float g = mx * mx;                     // E_G = 1
                const float ns = g_ns[t * WIN + w];
                const float expo = fmaxf(ns, g);             // relu(ns-g)+g
                acc1 += __expf(-0.5f * expo) * d2;           // SIGMA = 1
            }
        }
    }

    __shared__ float red[256];
    red[tid] = acc1 + 0.1f * acc2;   // E_THETA = 0.1
    __syncthreads();
    for (int st = 128; st > 0; st >>= 1) {
        if (tid < st) red[tid] += red[tid + st];
        __syncthreads();
    }
    if (tid == 0) g_partial[i] = red[0];
}

// ---------------------------------------------------------------------------
// Kernel C: final deterministic reduction of 4096 partials
// ---------------------------------------------------------------------------
__global__ __launch_bounds__(256) void k_final(float* __restrict__ out) {
    __shared__ double red[256];
    const int tid = threadIdx.x;
    double s = 0.0;
    for (int idx = tid; idx < BB; idx += 256) s += (double)g_partial[idx];
    red[tid] = s;
    __syncthreads();
    for (int st = 128; st > 0; st >>= 1) {
        if (tid < st) red[tid] += red[tid + st];
        __syncthreads();
    }
    if (tid == 0) out[0] = (float)(red[0] / (double)BB);  // E_ALPHA = 1
}

// ---------------------------------------------------------------------------
extern "C" void kernel_launch(void* const* d_in, const int* in_sizes, int n_in,
                              void* d_out, int out_size) {
    (void)in_sizes; (void)n_in; (void)out_size;
    const float* a  = (const float*)d_in[0];   // actioness   [4096,750]
    const float* a2 = (const float*)d_in[1];   // actioness_2 [4096,750]
    float* out = (float*)d_out;

    k_ns_part<<<NBZ, 256>>>(a);
    k_ns_reduce<<<(NSN + 255) / 256, 256>>>();
    k_ns_edge<<<31, 256>>>(a);
    k_mask<<<(TT + 255) / 256, 256>>>();
    k_main<<<BB, 256>>>(a, a2);
    k_final<<<1, 256>>>(out);
}

// round 7
// speedup vs baseline: 1.0139x; 1.0139x over previous
#include <cuda_runtime.h>
#include <math.h>

#define BB 4096
#define TT 750
#define WIN 11
#define NSN (TT * WIN)          // 8250
#define NBZ 256                 // blocks for ns partial pass
#define ROWS (BB / NBZ)         // 16 rows per block
#define TPAD 751                // smem row stride
#define NS_SKIP_THRESH 176.0f   // exp(-88): contribution negligible vs loss ~12.5

// Scratch (static device globals; no allocation allowed)
__device__ float g_ns_part[NBZ * NSN];   // 8.4 MB
__device__ float g_ns[NSN];
__device__ unsigned int g_mask[TT];
__device__ float g_partial[BB];
__device__ unsigned int g_done;          // zero-init; last block resets → replay-safe

// ---------------------------------------------------------------------------
// Kernel A: ns partials INCLUDING edge (scrambled-pad) terms.
// Block z owns rows [z*16, z*16+16). All 16 rows staged in smem in ONE bulk
// coalesced load phase (no per-row sync), then pure smem compute.
// Interior: ns[t][w] += (a[b,t] - a[b,t+w-6])^2 for 0 <= t+w-6 < 750.
// Edge (31 (t,w) pairs, j=t+w<6 or j>=756): pad = a[(6b+j)%B, 0] (front)
//   or a[(6b+j-755)%B, T-1] (back), matching the reference's tile-reshape.
// ---------------------------------------------------------------------------
__global__ __launch_bounds__(256) void k_ns_part(const float* __restrict__ a) {
    __shared__ float s[ROWS][TPAD];
    __shared__ float se[31];
    const int z = blockIdx.x;
    const int tid = threadIdx.x;
    const int b0 = z * ROWS;

    // Decode this thread's edge pair (threads 0..30)
    int et = 0, ew = 0, ej = 0;
    bool is_edge = (tid < 31);
    bool front = false;
    if (is_edge) {
        int p = tid;
        if (p < 21) {
            front = true;
            int acc = 0;
            for (int t = 0; t < 6; t++) {
                int c = 6 - t;
                if (p < acc + c) { et = t; ew = p - acc; break; }
                acc += c;
            }
        } else {
            int q = p - 21, acc = 0;
            for (int t = 746; t < 750; t++) {
                int c = t - 745;
                if (q < acc + c) { et = t; ew = (756 - t) + (q - acc); break; }
                acc += c;
            }
        }
        ej = et + ew;
    }

    // Prefetch edge pad values (issued before bulk load; latency fully hidden)
    float pv[ROWS];
    if (is_edge) {
#pragma unroll
        for (int r = 0; r < ROWS; r++) {
            const int b = b0 + r;
            size_t addr;
            if (front) addr = (size_t)((6 * b + ej) & (BB - 1)) * TT;
            else       addr = (size_t)((6 * b + (ej - 755)) & (BB - 1)) * TT + (TT - 1);
            pv[r] = __ldg(a + addr);
        }
    }

    // Bulk load: 16 rows x 750 floats, fully coalesced, massive MLP
    const float* __restrict__ base = a + (size_t)b0 * TT;
    for (int idx = tid; idx < ROWS * TT; idx += 256) {
        const int r = idx / TT;
        const int t = idx - r * TT;
        s[r][t] = base[(size_t)r * TT + t];
    }
    __syncthreads();

    // Interior accumulation: thread handles t = tid, tid+256, tid+512
    float acc[3][WIN];
#pragma unroll
    for (int k = 0; k < 3; k++)
#pragma unroll
        for (int w = 0; w < WIN; w++) acc[k][w] = 0.0f;

#pragma unroll 2
    for (int r = 0; r < ROWS; r++) {
#pragma unroll
        for (int k = 0; k < 3; k++) {
            const int t = tid + k * 256;
            if (t < TT) {
                const float at = s[r][t];
#pragma unroll
                for (int w = 0; w < WIN; w++) {
                    const int j = t + w - 6;
                    if (j >= 0 && j < TT) {
                        const float d = at - s[r][j];
                        acc[k][w] += d * d;
                    }
                }
            }
        }
    }

    // Edge accumulation (pads already in registers, a[b,t] in smem)
    if (is_edge) {
        float eacc = 0.0f;
#pragma unroll
        for (int r = 0; r < ROWS; r++) {
            const float d = s[r][et] - pv[r];
            eacc += d * d;
        }
        se[tid] = eacc;
    }
    __syncthreads();

    // Store partials; edge slots take se[] (their interior acc is 0 by guard)
#pragma unroll
    for (int k = 0; k < 3; k++) {
        const int t = tid + k * 256;
        if (t < TT) {
#pragma unroll
            for (int w = 0; w < WIN; w++) {
                const int j = t + w;
                float v;
                if (j < 6)         v = se[t * (13 - t) / 2 + w];
                else if (j >= 756) v = se[21 + (t - 746) * (t - 745) / 2 + (w - (756 - t))];
                else               v = acc[k][w];
                g_ns_part[(size_t)z * NSN + t * WIN + w] = v;
            }
        }
    }
}

// ---------------------------------------------------------------------------
// Kernel R: reduce 256 partials -> g_ns AND build per-t mask, fused.
// 63 blocks x 12 t each (132 slots/block) so every t's 11 w live in-block.
// Fixed-order summation -> deterministic.
// ---------------------------------------------------------------------------
__global__ __launch_bounds__(256) void k_reduce_mask() {
    const int t0 = blockIdx.x * 12;
    __shared__ float sns[132];
    const int tid = threadIdx.x;

    for (int li = tid; li < 132; li += 256) {
        const int idx = t0 * WIN + li;
        float sum = 0.0f;
        if (idx < NSN) {
            const float* __restrict__ p = g_ns_part + idx;
#pragma unroll 8
            for (int z = 0; z < NBZ; z++) sum += p[(size_t)z * NSN];
            g_ns[idx] = sum;
        }
        sns[li] = sum;
    }
    __syncthreads();

    if (tid < 12) {
        const int t = t0 + tid;
        if (t < TT) {
            unsigned m = 0;
#pragma unroll
            for (int w = 0; w < WIN; w++)
                if (sns[tid * WIN + w] <= NS_SKIP_THRESH) m |= (1u << w);
            g_mask[t] = m;
        }
    }
}

// ---------------------------------------------------------------------------
// Kernel M: main pass (block i = row i) + fused final reduction (last block).
//   term1_i = sum_{t,w} exp(-max(ns,g)/2) * |a2[i,t] - a3_win|  (filtered)
//   term2_i = sum_t (a[i,t]-a2[i,t])^2
// Filter: masked-out ns -> weight == 0 in f32; d2 == 0 -> term exactly 0.
// Surviving terms (none on this data, but faithful) take the full path.
// ---------------------------------------------------------------------------
__global__ __launch_bounds__(256) void k_main(const float* __restrict__ a,
                                              const float* __restrict__ a2,
                                              float* __restrict__ out) {
    const int i = blockIdx.x;
    const int tid = threadIdx.x;
    const float* __restrict__ ra  = a  + (size_t)i * TT;
    const float* __restrict__ ra2 = a2 + (size_t)i * TT;

    float acc1 = 0.0f;   // sum w*d2
    float acc2 = 0.0f;   // sum diff^2

    for (int t = tid; t < TT; t += 256) {
        const float av  = ra[t];
        const float a2v = ra2[t];
        const float dd = av - a2v;
        acc2 += dd * dd;

        unsigned m = g_mask[t];
        while (m) {
            const int w = __ffs(m) - 1;
            m &= m - 1;
            const int j = t + w;
            // a3_win (a2 with scrambled tile-pad)
            float a3w;
            if (j < 6)            a3w = a2[(size_t)((6 * i + j) & (BB - 1)) * TT];
            else if (j < TT + 6)  a3w = ra2[j - 6];
            else                  a3w = a2[(size_t)((6 * i + (j - 755)) & (BB - 1)) * TT + (TT - 1)];
            const float d2 = fabsf(a2v - a3w);
            if (d2 != 0.0f) {
                // Rare faithful path: g = (max_w2 (tiled - a4_win))^2
                float mx = -3.0e38f;
#pragma unroll
                for (int w2 = 0; w2 < WIN; w2++) {
                    const int j2 = t + w2;
                    float a4w;
                    if (j2 < 6)           a4w = a[(size_t)((6 * i + j2) & (BB - 1)) * TT];
                    else if (j2 < TT + 6) a4w = ra[j2 - 6];
                    else                  a4w = a[(size_t)((6 * i + (j2 - 755)) & (BB - 1)) * TT + (TT - 1)];
                    const float tv = a[(size_t)((11 * i + w2) & (BB - 1)) * TT + t];
                    mx = fmaxf(mx, tv - a4w);
                }
                const float g = mx * mx;                 // E_G = 1
                const float ns = g_ns[t * WIN + w];
                const float expo = fmaxf(ns, g);         // relu(ns-g)+g
                acc1 += __expf(-0.5f * expo) * d2;       // SIGMA = 1
            }
        }
    }

    __shared__ float red[256];
    red[tid] = acc1 + 0.1f * acc2;   // E_THETA = 0.1
    __syncthreads();
    for (int st = 128; st > 0; st >>= 1) {
        if (tid < st) red[tid] += red[tid + st];
        __syncthreads();
    }

    // Fused final reduction: last arriving block sums all partials (fixed order)
    __shared__ bool s_last;
    if (tid == 0) {
        g_partial[i] = red[0];
        __threadfence();
        const unsigned v = atomicAdd(&g_done, 1u);
        s_last = (v == BB - 1);
    }
    __syncthreads();

    if (s_last) {
        __shared__ double dred[256];
        double s = 0.0;
        for (int idx = tid; idx < BB; idx += 256) s += (double)g_partial[idx];
        dred[tid] = s;
        __syncthreads();
        for (int st = 128; st > 0; st >>= 1) {
            if (tid < st) dred[tid] += dred[tid + st];
            __syncthreads();
        }
        if (tid == 0) {
            out[0] = (float)(dred[0] / (double)BB);   // E_ALPHA = 1
            g_done = 0;                                // reset for next replay
        }
    }
}

// ---------------------------------------------------------------------------
extern "C" void kernel_launch(void* const* d_in, const int* in_sizes, int n_in,
                              void* d_out, int out_size) {
    (void)in_sizes; (void)n_in; (void)out_size;
    const float* a  = (const float*)d_in[0];   // actioness   [4096,750]
    const float* a2 = (const float*)d_in[1];   // actioness_2 [4096,750]
    float* out = (float*)d_out;

    k_ns_part<<<NBZ, 256>>>(a);
    k_reduce_mask<<<63, 256>>>();
    k_main<<<BB, 256>>>(a, a2, out);
}

// round 9
// speedup vs baseline: 1.0373x; 1.0231x over previous
#include <cuda_runtime.h>
#include <math.h>

#define BB 4096
#define TT 750
#define WIN 11
#define NSN (TT * WIN)          // 8250
#define NCHUNK 128              // row chunks
#define CROWS 32                // rows per chunk
#define TILE_T 250              // t-columns per tile (3 tiles = 750)
#define NOUT (TT * 6)           // 4500 S_d[t] outputs
#define MAIN_GRID 512           // k_main blocks (8 rows each)
#define NS_SKIP_THRESH 176.0f   // exp(-88): contribution negligible vs loss ~12.5

// Scratch (static device globals; no allocation allowed)
__device__ float g_part[(size_t)NOUT * NCHUNK];     // [o][z], 2.3 MB
__device__ float g_edge_part[31 * NCHUNK];          // [e][z]
__device__ float g_ns[NSN];
__device__ unsigned int g_mask[TT];
__device__ float g_bpart[MAIN_GRID];
__device__ unsigned int g_done;                     // zero-init; last block resets

// ---------------------------------------------------------------------------
// Kernel A: S_d partials, d=1..6.  S_d[t] = sum_b (a[b,t]-a[b,t+d])^2.
// Block = (chunk z of 32 rows) x (t-tile of 250 cols). Stage 32x256 tile in
// smem (cols t0..t0+255, halo 6), one sync, column-stationary accumulation.
// S_d[t] with t+d>749 is garbage but provably never consumed downstream.
// Edge (scrambled-pad) partials: tile0 computes the 21 front pairs, tile2 the
// 10 back pairs, for its own 32 rows. Pad values per reference's tile-reshape:
// front pad(b,j) = a[(6b+j)%B, 0]; back pad(b,j) = a[(6b+j-755)%B, T-1].
// ---------------------------------------------------------------------------
__global__ __launch_bounds__(256) void k_ns_part(const float* __restrict__ a) {
    __shared__ float s[CROWS][256];
    const int tile = blockIdx.x % 3;
    const int z    = blockIdx.x / 3;
    const int t0   = tile * TILE_T;
    const int b0   = z * CROWS;
    const int tid  = threadIdx.x;

    // Stage: per row, 32 consecutive lanes load 32 consecutive cols (coalesced)
    const int gc = t0 + tid;
    const bool cv = (gc < TT);
#pragma unroll
    for (int r = 0; r < CROWS; r++)
        s[r][tid] = cv ? a[(size_t)(b0 + r) * TT + gc] : 0.0f;
    __syncthreads();

    // Column-stationary accumulation
    float S[6] = {0.f, 0.f, 0.f, 0.f, 0.f, 0.f};
    const bool act = (tid < TILE_T);
    if (act) {
#pragma unroll 4
        for (int r = 0; r < CROWS; r++) {
            const float at = s[r][tid];
#pragma unroll
            for (int d = 1; d <= 6; d++) {
                const float df = at - s[r][tid + d];
                S[d - 1] += df * df;
            }
        }
    }

    // Edge partials
    if (tile == 0 && tid < 21) {
        int et = 0, ew = 0, acc = 0;
        for (int t = 0; t < 6; t++) {
            const int c = 6 - t;
            if (tid < acc + c) { et = t; ew = tid - acc; break; }
            acc += c;
        }
        const int j = et + ew;          // j < 6
        float eacc = 0.0f;
        for (int r0 = 0; r0 < CROWS; r0 += 8) {
            float pv[8];
#pragma unroll
            for (int k = 0; k < 8; k++)
                pv[k] = __ldg(a + (size_t)((6 * (b0 + r0 + k) + j) & (BB - 1)) * TT);
#pragma unroll
            for (int k = 0; k < 8; k++) {
                const float d = s[r0 + k][et] - pv[k];
                eacc += d * d;
            }
        }
        g_edge_part[tid * NCHUNK + z] = eacc;
    } else if (tile == 2 && tid < 10) {
        int et = 0, ew = 0, acc = 0;
        for (int t = 746; t < 750; t++) {
            const int c = t - 745;
            if (tid < acc + c) { et = t; ew = (756 - t) + (tid - acc); break; }
            acc += c;
        }
        const int j = et + ew;          // j >= 756
        const int col = et - t0;        // 246..249
        float eacc = 0.0f;
        for (int r0 = 0; r0 < CROWS; r0 += 8) {
            float pv[8];
#pragma unroll
            for (int k = 0; k < 8; k++)
                pv[k] = __ldg(a + (size_t)((6 * (b0 + r0 + k) + (j - 755)) & (BB - 1)) * TT + (TT - 1));
#pragma unroll
            for (int k = 0; k < 8; k++) {
                const float d = s[r0 + k][col] - pv[k];
                eacc += d * d;
            }
        }
        g_edge_part[(21 + tid) * NCHUNK + z] = eacc;
    }

    // Store partials [o][z]: o = t*6 + (d-1)
    if (act) {
        const int t = t0 + tid;
#pragma unroll
        for (int d = 1; d <= 6; d++)
            g_part[(size_t)(t * 6 + d - 1) * NCHUNK + z] = S[d - 1];
    }
}

// ---------------------------------------------------------------------------
// Kernel R: reduce partials -> g_ns (full [t][11]) + per-t mask, fused.
// Block handles 8 t's; computes S_d for t in [t0-6, t0+7] (halo) via
// warp-per-output coalesced contiguous sums. Edge sums in blocks 0 / last.
// Fixed-order sums -> deterministic.
// ---------------------------------------------------------------------------
__global__ __launch_bounds__(256) void k_reduce_mask() {
    const int t0 = blockIdx.x * 8;
    const int tid = threadIdx.x, lane = tid & 31, warp = tid >> 5;
    __shared__ float sS[14][6];
    __shared__ float sE[31];

    // 84 S outputs: tl=0..13 (t = t0-6+tl), d=1..6
    for (int o = warp; o < 84; o += 8) {
        const int tl = o / 6, dm = o % 6;
        const int tg = t0 - 6 + tl;
        float v = 0.0f;
        if (tg >= 0 && tg < TT) {
            const float* __restrict__ p = g_part + (size_t)(tg * 6 + dm) * NCHUNK;
#pragma unroll
            for (int k = 0; k < 4; k++) v += p[lane + 32 * k];
        }
#pragma unroll
        for (int off = 16; off; off >>= 1) v += __shfl_down_sync(0xffffffffu, v, off);
        if (lane == 0) sS[tl][dm] = v;
    }

    if (blockIdx.x == 0) {
        for (int e = warp; e < 21; e += 8) {
            const float* __restrict__ p = g_edge_part + (size_t)e * NCHUNK;
            float v = 0.0f;
#pragma unroll
            for (int k = 0; k < 4; k++) v += p[lane + 32 * k];
#pragma unroll
            for (int off = 16; off; off >>= 1) v += __shfl_down_sync(0xffffffffu, v, off);
            if (lane == 0) sE[e] = v;
        }
    } else if (blockIdx.x == gridDim.x - 1) {
        for (int e = 21 + warp; e < 31; e += 8) {
            const float* __restrict__ p = g_edge_part + (size_t)e * NCHUNK;
            float v = 0.0f;
#pragma unroll
            for (int k = 0; k < 4; k++) v += p[lane + 32 * k];
#pragma unroll
            for (int off = 16; off; off >>= 1) v += __shfl_down_sync(0xffffffffu, v, off);
            if (lane == 0) sE[e] = v;
        }
    }
    __syncthreads();

    if (tid < 8) {
        const int t = t0 + tid;
        if (t < TT) {
            unsigned m = 0;
#pragma unroll
            for (int w = 0; w < WIN; w++) {
                float v;
                if (w == 6) {
                    v = 0.0f;
                } else if (w > 6) {                       // d = w-6
                    if (t + w < 756) v = sS[tid + 6][w - 7];
                    else             v = sE[21 + (t - 746) * (t - 745) / 2 + (w - (756 - t))];
                } else {                                   // d = 6-w
                    const int d = 6 - w;
                    if (t - d >= 0) v = sS[tid + 6 - d][d - 1];
                    else            v = sE[t * (13 - t) / 2 + w];
                }
                g_ns[t * WIN + w] = v;
                if (v <= NS_SKIP_THRESH) m |= (1u << w);
            }
            g_mask[t] = m;
        }
    }
}

// ---------------------------------------------------------------------------
// Kernel M: main pass, warp-per-row (8 rows/block) + fused final reduction.
//   term1_i = sum_{t,w} exp(-max(ns,g)/2) * |a2[i,t] - a3_win|  (filtered)
//   term2_i = sum_t (a[i,t]-a2[i,t])^2
// Filter: masked-out ns -> weight == 0 in f32; d2 == 0 -> term exactly 0.
// Surviving terms (none on this data, but faithful) take the full path.
// ---------------------------------------------------------------------------
__global__ __launch_bounds__(256) void k_main(const float* __restrict__ a,
                                              const float* __restrict__ a2,
                                              float* __restrict__ out) {
    const int tid = threadIdx.x, lane = tid & 31, warp = tid >> 5;
    const int i = blockIdx.x * 8 + warp;
    const float* __restrict__ ra  = a  + (size_t)i * TT;
    const float* __restrict__ ra2 = a2 + (size_t)i * TT;

    float acc1 = 0.0f, acc2 = 0.0f;
    for (int t = lane; t < TT; t += 32) {
        const float av  = ra[t];
        const float a2v = ra2[t];
        const float dd = av - a2v;
        acc2 += dd * dd;

        unsigned m = g_mask[t];
        while (m) {
            const int w = __ffs(m) - 1;
            m &= m - 1;
            const int j = t + w;
            float a3w;
            if (j < 6)            a3w = a2[(size_t)((6 * i + j) & (BB - 1)) * TT];
            else if (j < TT + 6)  a3w = ra2[j - 6];
            else                  a3w = a2[(size_t)((6 * i + (j - 755)) & (BB - 1)) * TT + (TT - 1)];
            const float d2 = fabsf(a2v - a3w);
            if (d2 != 0.0f) {
                // Rare faithful path: g = (max_w2 (tiled - a4_win))^2
                float mx = -3.0e38f;
#pragma unroll
                for (int w2 = 0; w2 < WIN; w2++) {
                    const int j2 = t + w2;
                    float a4w;
                    if (j2 < 6)           a4w = a[(size_t)((6 * i + j2) & (BB - 1)) * TT];
                    else if (j2 < TT + 6) a4w = ra[j2 - 6];
                    else                  a4w = a[(size_t)((6 * i + (j2 - 755)) & (BB - 1)) * TT + (TT - 1)];
                    const float tv = a[(size_t)((11 * i + w2) & (BB - 1)) * TT + t];
                    mx = fmaxf(mx, tv - a4w);
                }
                const float g = mx * mx;                 // E_G = 1
                const float ns = g_ns[t * WIN + w];
                const float expo = fmaxf(ns, g);         // relu(ns-g)+g
                acc1 += __expf(-0.5f * expo) * d2;       // SIGMA = 1
            }
        }
    }

    float v = acc1 + 0.1f * acc2;                        // E_THETA = 0.1
#pragma unroll
    for (int off = 16; off; off >>= 1) v += __shfl_down_sync(0xffffffffu, v, off);

    __shared__ float sw[8];
    __shared__ bool s_last;
    if (lane == 0) sw[warp] = v;
    __syncthreads();
    if (tid == 0) {
        float bs = 0.0f;
#pragma unroll
        for (int k = 0; k < 8; k++) bs += sw[k];
        g_bpart[blockIdx.x] = bs;
        __threadfence();
        s_last = (atomicAdd(&g_done, 1u) == (unsigned)(gridDim.x - 1));
    }
    __syncthreads();

    if (s_last) {
        __shared__ double dred[256];
        double s = (double)g_bpart[tid] + (double)g_bpart[tid + 256];
        dred[tid] = s;
        __syncthreads();
        for (int st = 128; st; st >>= 1) {
            if (tid < st) dred[tid] += dred[tid + st];
            __syncthreads();
        }
        if (tid == 0) {
            out[0] = (float)(dred[0] / (double)BB);      // E_ALPHA = 1
            g_done = 0;                                  // reset for graph replay
        }
    }
}

// ---------------------------------------------------------------------------
extern "C" void kernel_launch(void* const* d_in, const int* in_sizes, int n_in,
                              void* d_out, int out_size) {
    (void)in_sizes; (void)n_in; (void)out_size;
    const float* a  = (const float*)d_in[0];   // actioness   [4096,750]
    const float* a2 = (const float*)d_in[1];   // actioness_2 [4096,750]
    float* out = (float*)d_out;

    k_ns_part<<<NCHUNK * 3, 256>>>(a);
    k_reduce_mask<<<(TT + 7) / 8, 256>>>();
    k_main<<<MAIN_GRID, 256>>>(a, a2, out);
}

// round 11
// speedup vs baseline: 2.4374x; 2.3498x over previous
#include <cuda_runtime.h>
#include <math.h>

#define BB 4096
#define TT 750
#define WIN 11
#define NSN (TT * WIN)          // 8250
#define NCHUNK 256              // row chunks (16 rows each)
#define CROWS 16
#define TILE_T 250              // t-columns per tile (3 tiles = 750)
#define NOUT (TT * 6)           // 4500 S_d[t] outputs
#define MAIN_GRID 512
#define NS_SKIP_THRESH 176.0f   // exp(-88): contribution negligible vs loss ~12.5

// Scratch (static device globals; no allocation allowed)
__device__ float g_part[(size_t)NCHUNK * NOUT];     // [z][o], 4.6 MB, o = t*6+(d-1)
__device__ float g_edge_part[31 * NCHUNK];          // [e][z]
__device__ float g_ns[NSN];
__device__ unsigned int g_mask[TT];                 // bits w != 6 only
__device__ unsigned int g_any;                      // OR of all masks
__device__ float g_bpart[MAIN_GRID];
__device__ unsigned int g_done;                     // zero-init; last block resets

// ---------------------------------------------------------------------------
// Kernel A: S_d partials, d=1..6.  S_d[t] = sum_b (a[b,t]-a[b,t+d])^2.
// Block = (chunk z of 16 rows) x (t-tile of 250 cols). 16x256 smem tile
// (6-col halo), one sync, column-stationary accumulation. Stores TRANSPOSED
// [z][o] so each thread writes 6 consecutive floats (coalesced).
// Edge (scrambled-pad) partials: tile0 -> 21 front pairs, tile2 -> 10 back,
// per reference pad: front(b,j)=a[(6b+j)%B,0]; back(b,j)=a[(6b+j-755)%B,T-1].
// ---------------------------------------------------------------------------
__global__ __launch_bounds__(256) void k_ns_part(const float* __restrict__ a) {
    __shared__ float s[CROWS][256];
    const int tile = blockIdx.x % 3;
    const int z    = blockIdx.x / 3;
    const int t0   = tile * TILE_T;
    const int b0   = z * CROWS;
    const int tid  = threadIdx.x;

    if (blockIdx.x == 0 && tid == 0) g_any = 0u;   // reset per replay (A runs first)

    // Stage (coalesced; halo cols >= 750 zeroed — provably never consumed)
    const int gc = t0 + tid;
    const bool cv = (gc < TT);
#pragma unroll
    for (int r = 0; r < CROWS; r++)
        s[r][tid] = cv ? a[(size_t)(b0 + r) * TT + gc] : 0.0f;
    __syncthreads();

    // Column-stationary accumulation
    float S[6] = {0.f, 0.f, 0.f, 0.f, 0.f, 0.f};
    const bool act = (tid < TILE_T);
    if (act) {
#pragma unroll 4
        for (int r = 0; r < CROWS; r++) {
            const float at = s[r][tid];
#pragma unroll
            for (int d = 1; d <= 6; d++) {
                const float df = at - s[r][tid + d];
                S[d - 1] += df * df;
            }
        }
    }

    // Edge partials
    if (tile == 0 && tid < 21) {
        int et = 0, ew = 0, acc = 0;
        for (int t = 0; t < 6; t++) {
            const int c = 6 - t;
            if (tid < acc + c) { et = t; ew = tid - acc; break; }
            acc += c;
        }
        const int j = et + ew;          // j < 6
        float eacc = 0.0f;
        for (int r0 = 0; r0 < CROWS; r0 += 8) {
            float pv[8];
#pragma unroll
            for (int k = 0; k < 8; k++)
                pv[k] = __ldg(a + (size_t)((6 * (b0 + r0 + k) + j) & (BB - 1)) * TT);
#pragma unroll
            for (int k = 0; k < 8; k++) {
                const float d = s[r0 + k][et] - pv[k];
                eacc += d * d;
            }
        }
        g_edge_part[tid * NCHUNK + z] = eacc;
    } else if (tile == 2 && tid < 10) {
        int et = 0, ew = 0, acc = 0;
        for (int t = 746; t < 750; t++) {
            const int c = t - 745;
            if (tid < acc + c) { et = t; ew = (756 - t) + (tid - acc); break; }
            acc += c;
        }
        const int j = et + ew;          // j >= 756
        const int col = et - t0;
        float eacc = 0.0f;
        for (int r0 = 0; r0 < CROWS; r0 += 8) {
            float pv[8];
#pragma unroll
            for (int k = 0; k < 8; k++)
                pv[k] = __ldg(a + (size_t)((6 * (b0 + r0 + k) + (j - 755)) & (BB - 1)) * TT + (TT - 1));
#pragma unroll
            for (int k = 0; k < 8; k++) {
                const float d = s[r0 + k][col] - pv[k];
                eacc += d * d;
            }
        }
        g_edge_part[(21 + tid) * NCHUNK + z] = eacc;
    }

    // Coalesced transposed store: thread writes 6 consecutive floats
    if (act) {
        const int t = t0 + tid;
        float* __restrict__ p = g_part + (size_t)z * NOUT + t * 6;
#pragma unroll
        for (int d = 0; d < 6; d++) p[d] = S[d];
    }
}

// ---------------------------------------------------------------------------
// Kernel R: reduce partials over z (coalesced contiguous loads), build
// g_ns[t][11], per-t mask (EXCLUDING w=6: that term is identically zero
// since j=t+6 is always interior so d2 == |a2[i,t]-a2[i,t]| == 0), and g_any.
// 21 blocks x 36 t each; thread owns one of 252 outputs (6-t halo below t0).
// Fixed-order z sum -> deterministic.
// ---------------------------------------------------------------------------
__global__ __launch_bounds__(256) void k_reduce_mask() {
    const int t0 = blockIdx.x * 36;
    const int o0 = t0 * 6 - 36;                 // include t0-6 .. t0-1 halo
    const int tid = threadIdx.x, lane = tid & 31, warp = tid >> 5;
    __shared__ float sS[252];
    __shared__ float sE[31];

    const int o = o0 + tid;
    float acc = 0.0f;
    if (tid < 252 && o >= 0 && o < NOUT) {
        const float* __restrict__ p = g_part + o;
#pragma unroll 8
        for (int z = 0; z < NCHUNK; z++) acc += p[(size_t)z * NOUT];
    }
    if (tid < 252) sS[tid] = acc;

    // Edge sums (blocks 0 and last); warp-per-e, coalesced over z
    if (blockIdx.x == 0) {
        for (int e = warp; e < 21; e += 8) {
            const float* __restrict__ p = g_edge_part + (size_t)e * NCHUNK;
            float v = 0.0f;
#pragma unroll
            for (int k = 0; k < 8; k++) v += p[lane + 32 * k];
#pragma unroll
            for (int off = 16; off; off >>= 1) v += __shfl_down_sync(0xffffffffu, v, off);
            if (lane == 0) sE[e] = v;
        }
    } else if (blockIdx.x == 20) {
        for (int e = 21 + warp; e < 31; e += 8) {
            const float* __restrict__ p = g_edge_part + (size_t)e * NCHUNK;
            float v = 0.0f;
#pragma unroll
            for (int k = 0; k < 8; k++) v += p[lane + 32 * k];
#pragma unroll
            for (int off = 16; off; off >>= 1) v += __shfl_down_sync(0xffffffffu, v, off);
            if (lane == 0) sE[e] = v;
        }
    }
    __syncthreads();

    if (tid < 36) {
        const int t = t0 + tid;
        if (t < TT) {
            unsigned m = 0;
#pragma unroll
            for (int w = 0; w < WIN; w++) {
                float v;
                if (w == 6) {
                    v = 0.0f;
                } else if (w > 6) {                     // d = w-6, S_d[t]
                    if (t + w < 756) v = sS[(t * 6 + (w - 6) - 1) - o0];
                    else             v = sE[21 + (t - 746) * (t - 745) / 2 + (w - (756 - t))];
                } else {                                // d = 6-w, S_d[t-d]
                    const int d = 6 - w;
                    if (t - d >= 0) v = sS[((t - d) * 6 + d - 1) - o0];
                    else            v = sE[t * (13 - t) / 2 + w];
                }
                g_ns[t * WIN + w] = v;
                if (w != 6 && v <= NS_SKIP_THRESH) m |= (1u << w);
            }
            g_mask[t] = m;
            if (m) atomicOr(&g_any, m);
        }
    }
}

// ---------------------------------------------------------------------------
// Kernel M: main pass, warp-per-row + fused final reduction.
// Fast path (g_any==0, the provable common case): term1 == 0 exactly
// (w=6 terms identically zero; all others have f32 weight 0) -> pure
// streaming sum of (a-a2)^2 with float2 loads.
// Slow path: faithful filtered evaluation as before.
// ---------------------------------------------------------------------------
__global__ __launch_bounds__(256) void k_main(const float* __restrict__ a,
                                              const float* __restrict__ a2,
                                              float* __restrict__ out) {
    const int tid = threadIdx.x, lane = tid & 31, warp = tid >> 5;
    const int i = blockIdx.x * 8 + warp;
    const float* __restrict__ ra  = a  + (size_t)i * TT;
    const float* __restrict__ ra2 = a2 + (size_t)i * TT;

    float acc1 = 0.0f, acc2 = 0.0f;
    const bool fast = (g_any == 0u);

    if (fast) {
        const float2* __restrict__ pa  = (const float2*)ra;   // 3000B rows: 8B aligned
        const float2* __restrict__ pa2 = (const float2*)ra2;
#pragma unroll 4
        for (int idx = lane; idx < TT / 2; idx += 32) {
            const float2 x = pa[idx];
            const float2 y = pa2[idx];
            const float d0 = x.x - y.x;
            const float d1 = x.y - y.y;
            acc2 += d0 * d0 + d1 * d1;
        }
    } else {
        for (int t = lane; t < TT; t += 32) {
            const float av  = ra[t];
            const float a2v = ra2[t];
            const float dd = av - a2v;
            acc2 += dd * dd;

            unsigned m = g_mask[t];
            while (m) {
                const int w = __ffs(m) - 1;
                m &= m - 1;
                const int j = t + w;
                float a3w;
                if (j < 6)            a3w = a2[(size_t)((6 * i + j) & (BB - 1)) * TT];
                else if (j < TT + 6)  a3w = ra2[j - 6];
                else                  a3w = a2[(size_t)((6 * i + (j - 755)) & (BB - 1)) * TT + (TT - 1)];
                const float d2 = fabsf(a2v - a3w);
                if (d2 != 0.0f) {
                    float mx = -3.0e38f;
#pragma unroll
                    for (int w2 = 0; w2 < WIN; w2++) {
                        const int j2 = t + w2;
                        float a4w;
                        if (j2 < 6)           a4w = a[(size_t)((6 * i + j2) & (BB - 1)) * TT];
                        else if (j2 < TT + 6) a4w = ra[j2 - 6];
                        else                  a4w = a[(size_t)((6 * i + (j2 - 755)) & (BB - 1)) * TT + (TT - 1)];
                        const float tv = a[(size_t)((11 * i + w2) & (BB - 1)) * TT + t];
                        mx = fmaxf(mx, tv - a4w);
                    }
                    const float g = mx * mx;             // E_G = 1
                    const float ns = g_ns[t * WIN + w];
                    const float expo = fmaxf(ns, g);     // relu(ns-g)+g
                    acc1 += __expf(-0.5f * expo) * d2;   // SIGMA = 1
                }
            }
        }
    }

    float v = acc1 + 0.1f * acc2;                        // E_THETA = 0.1
#pragma unroll
    for (int off = 16; off; off >>= 1) v += __shfl_down_sync(0xffffffffu, v, off);

    __shared__ float sw[8];
    __shared__ bool s_last;
    if (lane == 0) sw[warp] = v;
    __syncthreads();
    if (tid == 0) {
        float bs = 0.0f;
#pragma unroll
        for (int k = 0; k < 8; k++) bs += sw[k];
        g_bpart[blockIdx.x] = bs;
        __threadfence();
        s_last = (atomicAdd(&g_done, 1u) == (unsigned)(gridDim.x - 1));
    }
    __syncthreads();

    if (s_last) {
        __shared__ double dred[256];
        double s = (double)g_bpart[tid] + (double)g_bpart[tid + 256];
        dred[tid] = s;
        __syncthreads();
        for (int st = 128; st; st >>= 1) {
            if (tid < st) dred[tid] += dred[tid + st];
            __syncthreads();
        }
        if (tid == 0) {
            out[0] = (float)(dred[0] / (double)BB);      // E_ALPHA = 1
            g_done = 0;                                  // reset for graph replay
        }
    }
}

// ---------------------------------------------------------------------------
extern "C" void kernel_launch(void* const* d_in, const int* in_sizes, int n_in,
                              void* d_out, int out_size) {
    (void)in_sizes; (void)n_in; (void)out_size;
    const float* a  = (const float*)d_in[0];   // actioness   [4096,750]
    const float* a2 = (const float*)d_in[1];   // actioness_2 [4096,750]
    float* out = (float*)d_out;

    k_ns_part<<<NCHUNK * 3, 256>>>(a);
    k_reduce_mask<<<21, 256>>>();
    k_main<<<MAIN_GRID, 256>>>(a, a2, out);
}